// round 1
// baseline (speedup 1.0000x reference)
#include <cuda_runtime.h>
#include <math.h>

// Problem constants
#define T_STEPS 512
#define FUT     64
#define BATCH   1024
#define H       256
#define GRID    128
#define NTH     256
#define NTOT    (GRID * NTH)

// ---------------- device state (allocation-free scratch) ----------------
__device__ __align__(16) float d_h1[2][BATCH * H];
__device__ __align__(16) float d_c1[BATCH * H];
__device__ __align__(16) float d_h2[2][BATCH * H];
__device__ __align__(16) float d_c2[BATCH * H];
__device__ float d_h3[BATCH];
__device__ float d_c3[BATCH];

// Transposed/packed weights: index [kc*1024 + u], float4 over k within chunk.
__device__ float4 d_WT1 [64 * 1024];   // W_hh1^T packed
__device__ float4 d_WT2i[64 * 1024];   // W_ih2^T packed
__device__ float4 d_WT2h[64 * 1024];   // W_hh2^T packed

// grid barrier state
__device__ unsigned d_barcnt = 0;
__device__ volatile unsigned d_bargen = 0;

__device__ __forceinline__ void grid_sync() {
    __syncthreads();
    if (threadIdx.x == 0) {
        __threadfence();
        unsigned gen = d_bargen;
        if (atomicAdd(&d_barcnt, 1u) == GRID - 1u) {
            atomicExch(&d_barcnt, 0u);
            __threadfence();
            d_bargen = gen + 1u;
        } else {
            while (d_bargen == gen) { __nanosleep(64); }
        }
        __threadfence();
    }
    __syncthreads();
}

__device__ __forceinline__ float sigf(float z) { return 1.0f / (1.0f + expf(-z)); }

__device__ __forceinline__ float dot4(float4 s, float4 w, float a) {
    a = fmaf(s.x, w.x, a);
    a = fmaf(s.y, w.y, a);
    a = fmaf(s.z, w.z, a);
    a = fmaf(s.w, w.w, a);
    return a;
}

__global__ void __launch_bounds__(NTH, 1) lstm_kernel(
    const float* __restrict__ x,
    const float* __restrict__ Wih1, const float* __restrict__ Whh1,
    const float* __restrict__ bih1, const float* __restrict__ bhh1,
    const float* __restrict__ Wih2, const float* __restrict__ Whh2,
    const float* __restrict__ bih2, const float* __restrict__ bhh2,
    const float* __restrict__ Wih3, const float* __restrict__ Whh3,
    const float* __restrict__ bih3, const float* __restrict__ bhh3,
    float* __restrict__ out)
{
    extern __shared__ float4 smem[];
    float4* s_a = smem;          // 4096 float4 = 64KB  (64 rows x 64 float4)
    float4* s_b = smem + 4096;   // 4096 float4 = 64KB

    const int tid  = threadIdx.x;
    const int lane = tid & 31;
    const int warp = tid >> 5;
    const int cta  = blockIdx.x;
    const int bg   = cta >> 3;           // 0..15  (batch group of 64)
    const int jg   = cta & 7;            // 0..7   (unit group of 32)
    const int j    = jg * 32 + lane;     // 0..255 hidden unit
    const int gtid = cta * NTH + tid;

    // -------- per-launch init: zero states, pack weights --------
    for (int i = gtid; i < BATCH * H; i += NTOT) {
        d_h1[0][i] = 0.f; d_h1[1][i] = 0.f; d_c1[i] = 0.f;
        d_h2[0][i] = 0.f; d_h2[1][i] = 0.f; d_c2[i] = 0.f;
    }
    if (gtid < BATCH) { d_h3[gtid] = 0.f; d_c3[gtid] = 0.f; }
    for (int idx = gtid; idx < 64 * 1024; idx += NTOT) {
        int kc = idx >> 10, u = idx & 1023;
        const float* p = Whh1 + u * H + kc * 4;
        d_WT1[idx]  = make_float4(p[0], p[1], p[2], p[3]);
        p = Wih2 + u * H + kc * 4;
        d_WT2i[idx] = make_float4(p[0], p[1], p[2], p[3]);
        p = Whh2 + u * H + kc * 4;
        d_WT2h[idx] = make_float4(p[0], p[1], p[2], p[3]);
    }
    grid_sync();

    int parity = 0;
    for (int t = 0; t < T_STEPS + FUT; ++t) {
        const float* h1cur = d_h1[parity];
        float*       h1nxt = d_h1[parity ^ 1];
        const float* h2cur = d_h2[parity];
        float*       h2nxt = d_h2[parity ^ 1];

        // ================= phase 1: layer-1 cell =================
        for (int i = tid; i < 4096; i += NTH) {
            int r = i >> 6, c = i & 63;
            s_a[i] = reinterpret_cast<const float4*>(h1cur + (bg * 64 + r) * H)[c];
        }
        __syncthreads();
        {
            float ai[8], af[8], ag[8], ao[8];
            #pragma unroll
            for (int bb = 0; bb < 8; ++bb) { ai[bb]=0.f; af[bb]=0.f; ag[bb]=0.f; ao[bb]=0.f; }
            const float4* sw = s_a + (warp * 8) * 64;
            #pragma unroll 4
            for (int kc = 0; kc < 64; ++kc) {
                float4 wi = d_WT1[kc * 1024 +       j];
                float4 wf = d_WT1[kc * 1024 + 256 + j];
                float4 wg = d_WT1[kc * 1024 + 512 + j];
                float4 wo = d_WT1[kc * 1024 + 768 + j];
                #pragma unroll
                for (int bb = 0; bb < 8; ++bb) {
                    float4 s = sw[bb * 64 + kc];
                    ai[bb] = dot4(s, wi, ai[bb]);
                    af[bb] = dot4(s, wf, af[bb]);
                    ag[bb] = dot4(s, wg, ag[bb]);
                    ao[bb] = dot4(s, wo, ao[bb]);
                }
            }
            const float wv_i = Wih1[j],       wv_f = Wih1[256 + j];
            const float wv_g = Wih1[512 + j], wv_o = Wih1[768 + j];
            const float bi = bih1[j]       + bhh1[j];
            const float bf = bih1[256 + j] + bhh1[256 + j];
            const float bg_ = bih1[512 + j] + bhh1[512 + j];
            const float bo = bih1[768 + j] + bhh1[768 + j];
            #pragma unroll
            for (int bb = 0; bb < 8; ++bb) {
                int b = bg * 64 + warp * 8 + bb;
                float xin = (t < T_STEPS) ? x[t * BATCH + b] : d_c3[b];
                float zi = ai[bb] + xin * wv_i + bi;
                float zf = af[bb] + xin * wv_f + bf;
                float zg = ag[bb] + xin * wv_g + bg_;
                float zo = ao[bb] + xin * wv_o + bo;
                float co = d_c1[b * H + j];
                float cn = sigf(zf) * co + sigf(zi) * tanhf(zg);
                float hn = sigf(zo) * tanhf(cn);
                d_c1[b * H + j]  = cn;
                h1nxt[b * H + j] = hn;
            }
        }
        grid_sync();

        // ================= phase 2: layer-2 cell =================
        for (int i = tid; i < 4096; i += NTH) {
            int r = i >> 6, c = i & 63;
            s_a[i] = reinterpret_cast<const float4*>(d_c1 + (bg * 64 + r) * H)[c];
            s_b[i] = reinterpret_cast<const float4*>(h2cur + (bg * 64 + r) * H)[c];
        }
        __syncthreads();
        {
            float ai[8], af[8], ag[8], ao[8];
            #pragma unroll
            for (int bb = 0; bb < 8; ++bb) { ai[bb]=0.f; af[bb]=0.f; ag[bb]=0.f; ao[bb]=0.f; }
            const float4* swa = s_a + (warp * 8) * 64;
            const float4* swb = s_b + (warp * 8) * 64;
            #pragma unroll 4
            for (int kc = 0; kc < 64; ++kc) {
                float4 wi = d_WT2i[kc * 1024 +       j];
                float4 wf = d_WT2i[kc * 1024 + 256 + j];
                float4 wg = d_WT2i[kc * 1024 + 512 + j];
                float4 wo = d_WT2i[kc * 1024 + 768 + j];
                #pragma unroll
                for (int bb = 0; bb < 8; ++bb) {
                    float4 s = swa[bb * 64 + kc];
                    ai[bb] = dot4(s, wi, ai[bb]);
                    af[bb] = dot4(s, wf, af[bb]);
                    ag[bb] = dot4(s, wg, ag[bb]);
                    ao[bb] = dot4(s, wo, ao[bb]);
                }
            }
            #pragma unroll 4
            for (int kc = 0; kc < 64; ++kc) {
                float4 wi = d_WT2h[kc * 1024 +       j];
                float4 wf = d_WT2h[kc * 1024 + 256 + j];
                float4 wg = d_WT2h[kc * 1024 + 512 + j];
                float4 wo = d_WT2h[kc * 1024 + 768 + j];
                #pragma unroll
                for (int bb = 0; bb < 8; ++bb) {
                    float4 s = swb[bb * 64 + kc];
                    ai[bb] = dot4(s, wi, ai[bb]);
                    af[bb] = dot4(s, wf, af[bb]);
                    ag[bb] = dot4(s, wg, ag[bb]);
                    ao[bb] = dot4(s, wo, ao[bb]);
                }
            }
            const float bi = bih2[j]       + bhh2[j];
            const float bf = bih2[256 + j] + bhh2[256 + j];
            const float bg_ = bih2[512 + j] + bhh2[512 + j];
            const float bo = bih2[768 + j] + bhh2[768 + j];
            #pragma unroll
            for (int bb = 0; bb < 8; ++bb) {
                int b = bg * 64 + warp * 8 + bb;
                float zi = ai[bb] + bi;
                float zf = af[bb] + bf;
                float zg = ag[bb] + bg_;
                float zo = ao[bb] + bo;
                float co = d_c2[b * H + j];
                float cn = sigf(zf) * co + sigf(zi) * tanhf(zg);
                float hn = sigf(zo) * tanhf(cn);
                d_c2[b * H + j]  = cn;
                h2nxt[b * H + j] = hn;
            }
        }
        grid_sync();

        // ================= phase 3: layer-3 cell (H=1), warp-per-batch =================
        {
            int b = cta * 8 + warp;   // 128 CTAs * 8 warps = 1024 = BATCH
            const float* c2row = d_c2 + b * H;
            float a0 = 0.f, a1 = 0.f, a2 = 0.f, a3 = 0.f;
            #pragma unroll
            for (int kk = 0; kk < 8; ++kk) {
                int k = kk * 32 + lane;
                float v = c2row[k];
                a0 = fmaf(v, Wih3[0 * H + k], a0);
                a1 = fmaf(v, Wih3[1 * H + k], a1);
                a2 = fmaf(v, Wih3[2 * H + k], a2);
                a3 = fmaf(v, Wih3[3 * H + k], a3);
            }
            #pragma unroll
            for (int o = 16; o > 0; o >>= 1) {
                a0 += __shfl_xor_sync(0xFFFFFFFFu, a0, o);
                a1 += __shfl_xor_sync(0xFFFFFFFFu, a1, o);
                a2 += __shfl_xor_sync(0xFFFFFFFFu, a2, o);
                a3 += __shfl_xor_sync(0xFFFFFFFFu, a3, o);
            }
            if (lane == 0) {
                float h3o = d_h3[b], c3o = d_c3[b];
                float zi = a0 + h3o * Whh3[0] + bih3[0] + bhh3[0];
                float zf = a1 + h3o * Whh3[1] + bih3[1] + bhh3[1];
                float zg = a2 + h3o * Whh3[2] + bih3[2] + bhh3[2];
                float zo = a3 + h3o * Whh3[3] + bih3[3] + bhh3[3];
                float cn = sigf(zf) * c3o + sigf(zi) * tanhf(zg);
                float hn = sigf(zo) * tanhf(cn);
                d_c3[b] = cn;
                d_h3[b] = hn;
                if (t >= T_STEPS) out[b * FUT + (t - T_STEPS)] = cn;
            }
        }
        grid_sync();

        parity ^= 1;
    }
}

extern "C" void kernel_launch(void* const* d_in, const int* in_sizes, int n_in,
                              void* d_out, int out_size) {
    (void)in_sizes; (void)n_in; (void)out_size;
    const float* x    = (const float*)d_in[0];
    const float* Wih1 = (const float*)d_in[1];
    const float* Whh1 = (const float*)d_in[2];
    const float* bih1 = (const float*)d_in[3];
    const float* bhh1 = (const float*)d_in[4];
    const float* Wih2 = (const float*)d_in[5];
    const float* Whh2 = (const float*)d_in[6];
    const float* bih2 = (const float*)d_in[7];
    const float* bhh2 = (const float*)d_in[8];
    const float* Wih3 = (const float*)d_in[9];
    const float* Whh3 = (const float*)d_in[10];
    const float* bih3 = (const float*)d_in[11];
    const float* bhh3 = (const float*)d_in[12];

    cudaFuncSetAttribute(lstm_kernel, cudaFuncAttributeMaxDynamicSharedMemorySize, 135168);
    lstm_kernel<<<GRID, NTH, 131072>>>(x, Wih1, Whh1, bih1, bhh1,
                                       Wih2, Whh2, bih2, bhh2,
                                       Wih3, Whh3, bih3, bhh3,
                                       (float*)d_out);
}